// round 2
// baseline (speedup 1.0000x reference)
#include <cuda_runtime.h>

#define NN 100000
#define EE 1600000
#define H  128
#define NEGV (-1e30f)

// ---------------- device scratch (16B-aligned for float4 / red.v4) ----------------
__device__ __align__(16) float g_y[(size_t)NN * H];   // x @ W
__device__ __align__(16) float g_h[(size_t)NN * H];   // aggregated / post-relu features
__device__ __align__(16) float g_x[(size_t)NN * H];   // pooled features (next layer input)
__device__ float g_dinv[NN];
__device__ int   g_deg[NN];
__device__ float g_nm[NN];              // node mask (0/1)
__device__ float g_spre[NN];            // h @ ws
__device__ float g_score[NN];
__device__ unsigned long long g_key[NN];
__device__ int g_src[EE];
__device__ int g_dst[EE];
__device__ unsigned int g_hist[256];
__device__ unsigned long long g_prefix;
__device__ unsigned long long g_thresh;
__device__ int g_kremain;
__device__ int g_is64;
__device__ float g_sum[H];
__device__ float g_max[H];
__device__ float g_rtot[2 * H];

// ---------------- helpers ----------------
__device__ __forceinline__ void atomicMaxF(float* addr, float v) {
    int old = __float_as_int(*addr);
    while (__int_as_float(old) < v) {
        int prev = atomicCAS((int*)addr, old, __float_as_int(v));
        if (prev == old) break;
        old = prev;
    }
}

// ---------------- edge dtype detection + conversion ----------------
// If edge_index is really int64, the first 1024 values (src indices) are all in
// [0, NN). If it is int32 read as int64, each value is lo + (hi<<32) with hi a
// node index (in-range prob ~1e-5 per element) -> detection is unambiguous.
// Reads only the first 8KB, safe under either dtype.
__global__ void k_detect(const void* ei) {
    if (threadIdx.x == 0 && blockIdx.x == 0) {
        const long long* p = (const long long*)ei;
        int ok = 1;
        for (int i = 0; i < 1024; i++) {
            long long v = p[i];
            if (v < 0 || v >= NN) { ok = 0; break; }
        }
        g_is64 = ok;
    }
}

__global__ void k_convert_edges(const void* ei) {
    int i = blockIdx.x * blockDim.x + threadIdx.x;
    if (i >= EE) return;
    if (g_is64) {
        const long long* p = (const long long*)ei;
        g_src[i] = (int)p[i];
        g_dst[i] = (int)p[(size_t)EE + i];
    } else {
        const int* p = (const int*)ei;
        g_src[i] = p[i];
        g_dst[i] = p[(size_t)EE + i];
    }
}

// ---------------- init kernels ----------------
__global__ void k_global_init() {
    int i = blockIdx.x * blockDim.x + threadIdx.x;
    if (i < NN) g_nm[i] = 1.0f;
    if (i < 2 * H) g_rtot[i] = 0.0f;
}

__global__ void k_layer_init() {
    int i = blockIdx.x * blockDim.x + threadIdx.x;
    if (i < NN) g_deg[i] = 0;
    if (i < H) { g_sum[i] = 0.0f; g_max[i] = NEGV; }
}

// ---------------- degree / normalization ----------------
__global__ void k_degcount() {
    int e = blockIdx.x * blockDim.x + threadIdx.x;
    if (e >= EE) return;
    int s = g_src[e], d = g_dst[e];
    if (g_nm[s] > 0.5f && g_nm[d] > 0.5f) atomicAdd(&g_deg[d], 1);
}

__global__ void k_dinv() {
    int i = blockIdx.x * blockDim.x + threadIdx.x;
    if (i >= NN) return;
    g_dinv[i] = (g_nm[i] > 0.5f) ? rsqrtf((float)(1 + g_deg[i])) : 0.0f;
}

// ---------------- GEMM: g_y[N,128] = A[N,128] @ W[128,128] (fp32) ----------------
__global__ void __launch_bounds__(256) k_gemm(const float* __restrict__ xin,
                                              const float* __restrict__ Bm,
                                              int use_input) {
    __shared__ float As[128][17];
    __shared__ float Bs[16][128];
    const float* __restrict__ A = use_input ? xin : g_x;
    const int tid = threadIdx.x;
    const int tx = tid & 15;
    const int ty = tid >> 4;
    const int row0 = blockIdx.x * 128;
    float acc[8][8];
#pragma unroll
    for (int i = 0; i < 8; i++)
#pragma unroll
        for (int j = 0; j < 8; j++) acc[i][j] = 0.0f;

    for (int k0 = 0; k0 < 128; k0 += 16) {
#pragma unroll
        for (int l = 0; l < 2; l++) {
            int idx = tid + l * 256;          // float4 id 0..511
            int r = idx >> 2;                 // 0..127
            int c4 = idx & 3;                 // 0..3
            int gr = row0 + r;
            float4 v = make_float4(0.f, 0.f, 0.f, 0.f);
            if (gr < NN) v = *reinterpret_cast<const float4*>(A + (size_t)gr * 128 + k0 + c4 * 4);
            As[r][c4 * 4 + 0] = v.x; As[r][c4 * 4 + 1] = v.y;
            As[r][c4 * 4 + 2] = v.z; As[r][c4 * 4 + 3] = v.w;
        }
#pragma unroll
        for (int l = 0; l < 2; l++) {
            int idx = tid + l * 256;
            int r = idx >> 5;                 // 0..15
            int c4 = idx & 31;                // 0..31
            float4 v = *reinterpret_cast<const float4*>(Bm + (size_t)(k0 + r) * 128 + c4 * 4);
            *reinterpret_cast<float4*>(&Bs[r][c4 * 4]) = v;
        }
        __syncthreads();
#pragma unroll
        for (int kk = 0; kk < 16; kk++) {
            float a[8], bb[8];
#pragma unroll
            for (int i = 0; i < 8; i++) a[i] = As[ty * 8 + i][kk];
#pragma unroll
            for (int j = 0; j < 8; j++) bb[j] = Bs[kk][tx * 8 + j];
#pragma unroll
            for (int i = 0; i < 8; i++)
#pragma unroll
                for (int j = 0; j < 8; j++) acc[i][j] += a[i] * bb[j];
        }
        __syncthreads();
    }
#pragma unroll
    for (int i = 0; i < 8; i++) {
        int gr = row0 + ty * 8 + i;
        if (gr < NN) {
            float4 v0 = make_float4(acc[i][0], acc[i][1], acc[i][2], acc[i][3]);
            float4 v1 = make_float4(acc[i][4], acc[i][5], acc[i][6], acc[i][7]);
            *reinterpret_cast<float4*>(g_y + (size_t)gr * 128 + tx * 8) = v0;
            *reinterpret_cast<float4*>(g_y + (size_t)gr * 128 + tx * 8 + 4) = v1;
        }
    }
}

// ---------------- vector aggregation ----------------
__global__ void k_agg_init() {
    int idx = blockIdx.x * blockDim.x + threadIdx.x;   // over NN*32 float4s
    if (idx >= NN * 32) return;
    int row = idx >> 5;
    float di = g_dinv[row];
    float c = di * di;
    float4 v = reinterpret_cast<const float4*>(g_y)[idx];
    v.x *= c; v.y *= c; v.z *= c; v.w *= c;
    reinterpret_cast<float4*>(g_h)[idx] = v;
}

__global__ void k_agg_edges() {
    int w = (blockIdx.x * blockDim.x + threadIdx.x) >> 5;
    if (w >= EE) return;
    int lane = threadIdx.x & 31;
    int s = g_src[w], d = g_dst[w];
    float c = g_dinv[s] * g_dinv[d];
    if (c == 0.0f) return;
    float4 v = reinterpret_cast<const float4*>(g_y)[(size_t)s * 32 + lane];
    float4* hd = reinterpret_cast<float4*>(g_h) + (size_t)d * 32 + lane;
    asm volatile("red.global.add.v4.f32 [%0], {%1,%2,%3,%4};"
                 :: "l"(hd), "f"(v.x * c), "f"(v.y * c), "f"(v.z * c), "f"(v.w * c)
                 : "memory");
}

// h = relu(agg + b) * nm ; spre = h @ ws
__global__ void k_hpost_spre(const float* __restrict__ b, const float* __restrict__ ws) {
    int c = threadIdx.x;   // 128 threads
    __shared__ float red[4];
    float wc = ws[c];
    float bc = b[c];
    for (int row = blockIdx.x; row < NN; row += gridDim.x) {
        float nm = g_nm[row];
        float v = 0.0f;
        if (nm > 0.5f) v = fmaxf(g_h[(size_t)row * H + c] + bc, 0.0f);
        g_h[(size_t)row * H + c] = v;
        float p = v * wc;
#pragma unroll
        for (int o = 16; o > 0; o >>= 1) p += __shfl_down_sync(0xffffffffu, p, o);
        if ((c & 31) == 0) red[c >> 5] = p;
        __syncthreads();
        if (c == 0) g_spre[row] = red[0] + red[1] + red[2] + red[3];
        __syncthreads();
    }
}

// ---------------- scalar score aggregation ----------------
__global__ void k_score_init() {
    int i = blockIdx.x * blockDim.x + threadIdx.x;
    if (i >= NN) return;
    float di = g_dinv[i];
    g_score[i] = di * di * g_spre[i];
}

__global__ void k_score_edges() {
    int e = blockIdx.x * blockDim.x + threadIdx.x;
    if (e >= EE) return;
    int s = g_src[e], d = g_dst[e];
    float c = g_dinv[s] * g_dinv[d];
    if (c != 0.0f) atomicAdd(&g_score[d], c * g_spre[s]);
}

__global__ void k_keygen(const float* __restrict__ bs) {
    int i = blockIdx.x * blockDim.x + threadIdx.x;
    if (i >= NN) return;
    float sc = g_score[i] + bs[0];
    g_score[i] = sc;
    unsigned int u = __float_as_uint(sc);
    unsigned int k32 = (u & 0x80000000u) ? ~u : (u | 0x80000000u);
    if (g_nm[i] <= 0.5f) k32 = 0u;
    g_key[i] = ((unsigned long long)k32 << 32) | (unsigned int)(~(unsigned int)i);
}

// ---------------- radix select (top-k) ----------------
__global__ void k_select_init(int k) {
    g_hist[threadIdx.x] = 0u;
    if (threadIdx.x == 0) { g_prefix = 0ULL; g_kremain = k; }
}

__global__ void k_hist(int shift, int first) {
    __shared__ unsigned int sh[256];
    if (threadIdx.x < 256) sh[threadIdx.x] = 0u;
    __syncthreads();
    unsigned long long pref = g_prefix;
    for (int i = blockIdx.x * blockDim.x + threadIdx.x; i < NN; i += gridDim.x * blockDim.x) {
        unsigned long long key = g_key[i];
        if (first || (((key ^ pref) >> (shift + 8)) == 0ULL))
            atomicAdd(&sh[(unsigned int)(key >> shift) & 0xFFu], 1u);
    }
    __syncthreads();
    if (threadIdx.x < 256) {
        unsigned int v = sh[threadIdx.x];
        if (v) atomicAdd(&g_hist[threadIdx.x], v);
    }
}

__global__ void k_step(int shift) {
    __shared__ unsigned int h[256];
    int t = threadIdx.x;
    h[t] = g_hist[t];
    g_hist[t] = 0u;       // ready for next pass
    __syncthreads();
    if (t == 0) {
        int krem = g_kremain;
        unsigned int cum = 0;
        int b = 255;
        for (; b > 0; b--) {
            cum += h[b];
            if ((int)cum >= krem) break;
        }
        if ((int)cum < krem) cum += h[0];      // b == 0 fallthrough
        g_prefix |= ((unsigned long long)(unsigned int)b) << shift;
        g_kremain = krem - (int)(cum - h[b]);
        if (shift == 0) g_thresh = g_prefix;
    }
}

// ---------------- pool + readout ----------------
__global__ void k_pool_readout() {
    int c = threadIdx.x;   // 128
    unsigned long long thr = g_thresh;
    float accS = 0.0f, accM = NEGV;
    for (int row = blockIdx.x; row < NN; row += gridDim.x) {
        bool sel = g_key[row] >= thr;
        float t = sel ? tanhf(g_score[row]) : 0.0f;
        float v = g_h[(size_t)row * H + c] * t;
        g_x[(size_t)row * H + c] = v;
        if (c == 0) g_nm[row] = sel ? 1.0f : 0.0f;
        if (sel) { accS += v; accM = fmaxf(accM, v); }
    }
    atomicAdd(&g_sum[c], accS);
    atomicMaxF(&g_max[c], accM);
}

__global__ void k_readout_add(float kf) {
    int t = threadIdx.x;   // 256
    if (t < H) g_rtot[t] += g_sum[t] / kf;
    else g_rtot[t] += g_max[t - H];
}

// ---------------- final MLP + log_softmax ----------------
__global__ void k_mlp(const float* __restrict__ M1, const float* __restrict__ bm1,
                      const float* __restrict__ M2, const float* __restrict__ bm2,
                      const float* __restrict__ M3, const float* __restrict__ bm3,
                      float* __restrict__ out) {
    __shared__ float r[256];
    __shared__ float y1[128];
    __shared__ float y2[64];
    __shared__ float y3[10];
    int t = threadIdx.x;   // 256
    r[t] = g_rtot[t];
    __syncthreads();
    if (t < 128) {
        float a = bm1[t];
        for (int i = 0; i < 256; i++) a += r[i] * M1[i * 128 + t];
        y1[t] = fmaxf(a, 0.0f);
    }
    __syncthreads();
    if (t < 64) {
        float a = bm2[t];
        for (int i = 0; i < 128; i++) a += y1[i] * M2[i * 64 + t];
        y2[t] = fmaxf(a, 0.0f);
    }
    __syncthreads();
    if (t < 10) {
        float a = bm3[t];
        for (int i = 0; i < 64; i++) a += y2[i] * M3[i * 10 + t];
        y3[t] = a;
    }
    __syncthreads();
    if (t == 0) {
        float m = y3[0];
        for (int j = 1; j < 10; j++) m = fmaxf(m, y3[j]);
        float s = 0.0f;
        for (int j = 0; j < 10; j++) s += expf(y3[j] - m);
        float l = logf(s);
        for (int j = 0; j < 10; j++) out[j] = y3[j] - m - l;
    }
}

// ---------------- launch ----------------
extern "C" void kernel_launch(void* const* d_in, const int* in_sizes, int n_in,
                              void* d_out, int out_size) {
    const float* x = (const float*)d_in[0];
    const void* ei = d_in[1];
    const float* W[3]  = {(const float*)d_in[2], (const float*)d_in[6], (const float*)d_in[10]};
    const float* b[3]  = {(const float*)d_in[3], (const float*)d_in[7], (const float*)d_in[11]};
    const float* ws[3] = {(const float*)d_in[4], (const float*)d_in[8], (const float*)d_in[12]};
    const float* bs[3] = {(const float*)d_in[5], (const float*)d_in[9], (const float*)d_in[13]};
    const float* M1 = (const float*)d_in[14]; const float* bm1 = (const float*)d_in[15];
    const float* M2 = (const float*)d_in[16]; const float* bm2 = (const float*)d_in[17];
    const float* M3 = (const float*)d_in[18]; const float* bm3 = (const float*)d_in[19];
    float* out = (float*)d_out;

    const int kk[3] = {50000, 25000, 12500};
    const int gN  = (NN + 255) / 256;
    const int gE  = (EE + 255) / 256;
    const int gNH = (NN * 32 + 255) / 256;
    const int gEW = (EE * 32 + 255) / 256;   // warp per edge

    k_detect<<<1, 32>>>(ei);
    k_convert_edges<<<gE, 256>>>(ei);
    k_global_init<<<gN, 256>>>();

    for (int L = 0; L < 3; L++) {
        k_layer_init<<<gN, 256>>>();
        k_degcount<<<gE, 256>>>();
        k_dinv<<<gN, 256>>>();
        k_gemm<<<(NN + 127) / 128, 256>>>(x, W[L], L == 0 ? 1 : 0);
        k_agg_init<<<gNH, 256>>>();
        k_agg_edges<<<gEW, 256>>>();
        k_hpost_spre<<<2048, 128>>>(b[L], ws[L]);
        k_score_init<<<gN, 256>>>();
        k_score_edges<<<gE, 256>>>();
        k_keygen<<<gN, 256>>>(bs[L]);
        k_select_init<<<1, 256>>>(kk[L]);
        for (int shift = 56; shift >= 0; shift -= 8) {
            k_hist<<<512, 256>>>(shift, shift == 56 ? 1 : 0);
            k_step<<<1, 256>>>(shift);
        }
        k_pool_readout<<<1024, 128>>>();
        k_readout_add<<<1, 256>>>((float)kk[L]);
    }
    k_mlp<<<1, 256>>>(M1, bm1, M2, bm2, M3, bm3, out);
}

// round 3
// speedup vs baseline: 2.3398x; 2.3398x over previous
#include <cuda_runtime.h>

#define NN 100000
#define EE 1600000
#define H  128
#define NEGV (-1e30f)
#define SB 128
#define ST 256

// ---------------- device scratch ----------------
__device__ __align__(16) float g_x[(size_t)NN * H];   // compact pooled features
__device__ __align__(16) float g_y[(size_t)NN * H];   // dinv * (A @ W)
__device__ __align__(16) float g_h[(size_t)NN * H];   // relu(agg + b)
__device__ float g_dinv[NN];
__device__ int   g_deg[NN];
__device__ int   g_rowptr[NN + 1];
__device__ int   g_cursor[NN];
__device__ float g_sp2[NN];                            // dinv * (h @ ws)
__device__ float g_score[NN];
__device__ unsigned long long g_key[NN];
__device__ int g_cmap[NN];
__device__ int g_sel[NN];
__device__ int g_ea_src[EE], g_ea_dst[EE];
__device__ int g_eb_src[EE], g_eb_dst[EE];
__device__ int g_msize[4];
__device__ unsigned int g_hist[256];
__device__ unsigned long long g_prefix;
__device__ unsigned long long g_thresh;
__device__ int g_kremain;
__device__ int g_is64;
__device__ int g_bsum[SB];
__device__ float g_sum[H], g_max[H], g_rtot[2 * H];
__device__ unsigned int g_barcnt;
__device__ volatile unsigned int g_bargen;

// ---------------- helpers ----------------
__device__ __forceinline__ void atomicMaxF(float* addr, float v) {
    int old = __float_as_int(*addr);
    while (__int_as_float(old) < v) {
        int prev = atomicCAS((int*)addr, old, __float_as_int(v));
        if (prev == old) break;
        old = prev;
    }
}

// software grid barrier — only for kernels launched with exactly SB blocks
// (SB=128 <= 148 SMs, 1 block/SM min occupancy -> single wave, deadlock-free)
__device__ __forceinline__ void gridbar() {
    __syncthreads();
    if (threadIdx.x == 0) {
        unsigned int gen = g_bargen;
        if (atomicAdd(&g_barcnt, 1u) == (unsigned)gridDim.x - 1u) {
            g_barcnt = 0u;
            __threadfence();
            g_bargen = gen + 1u;
        } else {
            while (g_bargen == gen) __nanosleep(64);
        }
    }
    __syncthreads();
}

// ---------------- edge dtype detect + convert ----------------
__global__ void k_detect(const void* ei) {
    if (threadIdx.x == 0 && blockIdx.x == 0) {
        const long long* p = (const long long*)ei;
        int ok = 1;
        for (int i = 0; i < 1024; i++) {
            long long v = p[i];
            if (v < 0 || v >= NN) { ok = 0; break; }
        }
        g_is64 = ok;
    }
}

__global__ void k_convert(const void* ei) {
    int i = blockIdx.x * blockDim.x + threadIdx.x;
    if (i >= EE) return;
    if (g_is64) {
        const long long* p = (const long long*)ei;
        g_ea_src[i] = (int)p[i];
        g_ea_dst[i] = (int)p[(size_t)EE + i];
    } else {
        const int* p = (const int*)ei;
        g_ea_src[i] = p[i];
        g_ea_dst[i] = p[(size_t)EE + i];
    }
}

__global__ void k_init() {
    int i = blockIdx.x * blockDim.x + threadIdx.x;
    if (i < NN) g_deg[i] = 0;
    if (i < H) { g_sum[i] = 0.0f; g_max[i] = NEGV; }
    if (i < 2 * H) g_rtot[i] = 0.0f;
    if (i == 0) { g_msize[0] = EE; g_barcnt = 0u; }
}

// ---------------- edge passes ----------------
__global__ void k_deg(const int* __restrict__ ps, const int* __restrict__ pd,
                      int midx, int use_cmap) {
    int e = blockIdx.x * blockDim.x + threadIdx.x;
    if (e >= g_msize[midx]) return;
    int s = ps[e], d = pd[e];
    if (use_cmap) {
        s = g_cmap[s]; d = g_cmap[d];
        if (s < 0 || d < 0) return;
    }
    atomicAdd(&g_deg[d], 1);
}

__global__ void k_scatter(const int* __restrict__ ps, const int* __restrict__ pd,
                          int* __restrict__ gs, int* __restrict__ gd,
                          int midx, int use_cmap) {
    int e = blockIdx.x * blockDim.x + threadIdx.x;
    if (e >= g_msize[midx]) return;
    int s = ps[e], d = pd[e];
    if (use_cmap) {
        s = g_cmap[s]; d = g_cmap[d];
        if (s < 0 || d < 0) return;
    }
    int pos = atomicAdd(&g_cursor[d], 1);
    gs[pos] = s;
    gd[pos] = d;
}

// ---------------- persistent scan: rowptr/cursor/dinv/msize ----------------
__global__ void __launch_bounds__(ST) k_scan_dinv(int n, int lidx) {
    __shared__ int s1[ST];
    const int tid = threadIdx.x, bid = blockIdx.x;
    const int gt = bid * ST + tid;
    const int gs = SB * ST;
    const int c = (n + gs - 1) / gs;
    const int lo = min(gt * c, n), hi = min(lo + c, n);
    int cnt = 0;
    for (int i = lo; i < hi; i++) cnt += g_deg[i];
    s1[tid] = cnt; __syncthreads();
    for (int off = 1; off < ST; off <<= 1) {
        int v = (tid >= off) ? s1[tid - off] : 0;
        __syncthreads();
        s1[tid] += v;
        __syncthreads();
    }
    int tpre = s1[tid] - cnt;
    if (tid == 0) g_bsum[bid] = s1[ST - 1];
    gridbar();
    if (bid == 0 && tid == 0) {
        int a = 0;
        for (int bb = 0; bb < SB; bb++) { int t = __ldcg(&g_bsum[bb]); g_bsum[bb] = a; a += t; }
        g_msize[lidx] = a;
        g_rowptr[n] = a;
    }
    gridbar();
    int base = __ldcg(&g_bsum[bid]) + tpre;
    for (int i = lo; i < hi; i++) {
        int d = g_deg[i];
        g_rowptr[i] = base;
        g_cursor[i] = base;
        g_dinv[i] = rsqrtf((float)(1 + d));
        base += d;
    }
}

// ---------------- GEMM: g_y[n,128] = dinv * (A[n,128] @ W[128,128]) ----------------
__global__ void __launch_bounds__(256) k_gemm(const float* __restrict__ xin,
                                              const float* __restrict__ Bm, int n) {
    __shared__ float As[128][17];
    __shared__ float Bs[16][128];
    const float* __restrict__ A = xin ? xin : g_x;
    const int tid = threadIdx.x;
    const int tx = tid & 15;
    const int ty = tid >> 4;
    const int row0 = blockIdx.x * 128;
    float acc[8][8];
#pragma unroll
    for (int i = 0; i < 8; i++)
#pragma unroll
        for (int j = 0; j < 8; j++) acc[i][j] = 0.0f;

    for (int k0 = 0; k0 < 128; k0 += 16) {
#pragma unroll
        for (int l = 0; l < 2; l++) {
            int idx = tid + l * 256;
            int r = idx >> 2;
            int c4 = idx & 3;
            int gr = row0 + r;
            float4 v = make_float4(0.f, 0.f, 0.f, 0.f);
            if (gr < n) v = *reinterpret_cast<const float4*>(A + (size_t)gr * 128 + k0 + c4 * 4);
            As[r][c4 * 4 + 0] = v.x; As[r][c4 * 4 + 1] = v.y;
            As[r][c4 * 4 + 2] = v.z; As[r][c4 * 4 + 3] = v.w;
        }
#pragma unroll
        for (int l = 0; l < 2; l++) {
            int idx = tid + l * 256;
            int r = idx >> 5;
            int c4 = idx & 31;
            float4 v = *reinterpret_cast<const float4*>(Bm + (size_t)(k0 + r) * 128 + c4 * 4);
            *reinterpret_cast<float4*>(&Bs[r][c4 * 4]) = v;
        }
        __syncthreads();
#pragma unroll
        for (int kk = 0; kk < 16; kk++) {
            float a[8], bb[8];
#pragma unroll
            for (int i = 0; i < 8; i++) a[i] = As[ty * 8 + i][kk];
#pragma unroll
            for (int j = 0; j < 8; j++) bb[j] = Bs[kk][tx * 8 + j];
#pragma unroll
            for (int i = 0; i < 8; i++)
#pragma unroll
                for (int j = 0; j < 8; j++) acc[i][j] += a[i] * bb[j];
        }
        __syncthreads();
    }
#pragma unroll
    for (int i = 0; i < 8; i++) {
        int gr = row0 + ty * 8 + i;
        if (gr < n) {
            float di = g_dinv[gr];
            float4 v0 = make_float4(acc[i][0] * di, acc[i][1] * di, acc[i][2] * di, acc[i][3] * di);
            float4 v1 = make_float4(acc[i][4] * di, acc[i][5] * di, acc[i][6] * di, acc[i][7] * di);
            *reinterpret_cast<float4*>(g_y + (size_t)gr * 128 + tx * 8) = v0;
            *reinterpret_cast<float4*>(g_y + (size_t)gr * 128 + tx * 8 + 4) = v1;
        }
    }
}

// ---------------- CSR aggregation fused with bias+relu+score-projection ----------------
__global__ void __launch_bounds__(256) k_agg(const float* __restrict__ bv,
                                             const float* __restrict__ ws,
                                             const int* __restrict__ gsrc, int n) {
    int w = (blockIdx.x * 256 + threadIdx.x) >> 5;
    int lane = threadIdx.x & 31;
    if (w >= n) return;
    float di = g_dinv[w];
    int r0 = g_rowptr[w], r1 = g_rowptr[w + 1];
    float4 acc = reinterpret_cast<const float4*>(g_y)[(size_t)w * 32 + lane];  // self term
    for (int e = r0; e < r1; e++) {
        int s = gsrc[e];
        float4 v = reinterpret_cast<const float4*>(g_y)[(size_t)s * 32 + lane];
        acc.x += v.x; acc.y += v.y; acc.z += v.z; acc.w += v.w;
    }
    float4 bb = reinterpret_cast<const float4*>(bv)[lane];
    float4 hv;
    hv.x = fmaxf(di * acc.x + bb.x, 0.0f);
    hv.y = fmaxf(di * acc.y + bb.y, 0.0f);
    hv.z = fmaxf(di * acc.z + bb.z, 0.0f);
    hv.w = fmaxf(di * acc.w + bb.w, 0.0f);
    reinterpret_cast<float4*>(g_h)[(size_t)w * 32 + lane] = hv;
    float4 wv = reinterpret_cast<const float4*>(ws)[lane];
    float p = hv.x * wv.x + hv.y * wv.y + hv.z * wv.z + hv.w * wv.w;
#pragma unroll
    for (int o = 16; o > 0; o >>= 1) p += __shfl_down_sync(0xffffffffu, p, o);
    if (lane == 0) g_sp2[w] = di * p;
}

// ---------------- scalar score via CSR ----------------
__global__ void k_score(const int* __restrict__ gsrc, const float* __restrict__ bs, int n) {
    int d = blockIdx.x * blockDim.x + threadIdx.x;
    if (d >= n) return;
    float di = g_dinv[d];
    float acc = g_sp2[d];
    int r0 = g_rowptr[d], r1 = g_rowptr[d + 1];
    for (int e = r0; e < r1; e++) acc += g_sp2[gsrc[e]];
    g_score[d] = di * acc + bs[0];
}

// ---------------- persistent select: keygen + radix topk + compact + pool + readout ----------------
__global__ void __launch_bounds__(ST) k_select(int n, int k) {
    __shared__ unsigned int sh[256];
    __shared__ int s1[ST];
    const int tid = threadIdx.x, bid = blockIdx.x;
    const int gt = bid * ST + tid;
    const int gs = SB * ST;

    // keygen: orderable float desc, tie-break by smaller index
    for (int i = gt; i < n; i += gs) {
        unsigned int u = __float_as_uint(g_score[i]);
        unsigned int k32 = (u & 0x80000000u) ? ~u : (u | 0x80000000u);
        g_key[i] = ((unsigned long long)k32 << 32) | (unsigned int)(~(unsigned int)i);
    }
    if (bid == 0) {
        g_hist[tid] = 0u;
        if (tid == 0) { g_prefix = 0ULL; g_kremain = k; }
    }
    gridbar();

    // 8-pass radix select (MSB first)
    for (int shift = 56; shift >= 0; shift -= 8) {
        sh[tid] = 0u;
        __syncthreads();
        bool first = (shift == 56);
        unsigned long long pref = first ? 0ULL : __ldcg(&g_prefix);
        for (int i = gt; i < n; i += gs) {
            unsigned long long key = g_key[i];
            if (first || ((key ^ pref) >> (shift + 8)) == 0ULL)
                atomicAdd(&sh[(unsigned int)(key >> shift) & 255u], 1u);
        }
        __syncthreads();
        if (sh[tid]) atomicAdd(&g_hist[tid], sh[tid]);
        gridbar();
        if (bid == 0) {
            unsigned int hv = __ldcg(&g_hist[tid]);
            g_hist[tid] = 0u;   // ready for next pass
            sh[tid] = hv;
            __syncthreads();
            if (tid == 0) {
                int krem = g_kremain;
                unsigned int cum = 0; int b = 255;
                for (; b > 0; b--) { cum += sh[b]; if ((int)cum >= krem) break; }
                if ((int)cum < krem) cum += sh[0];
                g_prefix |= ((unsigned long long)(unsigned int)b) << shift;
                g_kremain = krem - (int)(cum - sh[b]);
                if (shift == 0) g_thresh = g_prefix;
            }
        }
        gridbar();
    }
    const unsigned long long thr = __ldcg(&g_thresh);

    // order-preserving compaction: cmap + sel list
    const int c = (n + gs - 1) / gs;
    const int lo = min(gt * c, n), hi = min(lo + c, n);
    int cnt = 0;
    for (int i = lo; i < hi; i++) cnt += (g_key[i] >= thr) ? 1 : 0;
    s1[tid] = cnt; __syncthreads();
    for (int off = 1; off < ST; off <<= 1) {
        int v = (tid >= off) ? s1[tid - off] : 0;
        __syncthreads();
        s1[tid] += v;
        __syncthreads();
    }
    int tpre = s1[tid] - cnt;
    if (tid == 0) g_bsum[bid] = s1[ST - 1];
    gridbar();
    if (bid == 0 && tid == 0) {
        int a = 0;
        for (int bb = 0; bb < SB; bb++) { int t = __ldcg(&g_bsum[bb]); g_bsum[bb] = a; a += t; }
    }
    gridbar();
    int base = __ldcg(&g_bsum[bid]) + tpre;
    for (int i = lo; i < hi; i++) {
        bool s = (g_key[i] >= thr);
        g_cmap[i] = s ? base : -1;
        if (s) { g_sel[base] = i; base++; }
    }
    gridbar();

    // pool + readout: warp per new compact row
    int w = gt >> 5, lane = gt & 31, nw = gs >> 5;
    float4 aS = make_float4(0.f, 0.f, 0.f, 0.f);
    float4 aM = make_float4(NEGV, NEGV, NEGV, NEGV);
    for (int j = w; j < k; j += nw) {
        int i = g_sel[j];
        float t = tanhf(g_score[i]);
        float4 v = reinterpret_cast<const float4*>(g_h)[(size_t)i * 32 + lane];
        v.x *= t; v.y *= t; v.z *= t; v.w *= t;
        reinterpret_cast<float4*>(g_x)[(size_t)j * 32 + lane] = v;
        aS.x += v.x; aS.y += v.y; aS.z += v.z; aS.w += v.w;
        aM.x = fmaxf(aM.x, v.x); aM.y = fmaxf(aM.y, v.y);
        aM.z = fmaxf(aM.z, v.z); aM.w = fmaxf(aM.w, v.w);
    }
    int col = lane * 4;
    atomicAdd(&g_sum[col + 0], aS.x);
    atomicAdd(&g_sum[col + 1], aS.y);
    atomicAdd(&g_sum[col + 2], aS.z);
    atomicAdd(&g_sum[col + 3], aS.w);
    atomicMaxF(&g_max[col + 0], aM.x);
    atomicMaxF(&g_max[col + 1], aM.y);
    atomicMaxF(&g_max[col + 2], aM.z);
    atomicMaxF(&g_max[col + 3], aM.w);
    // zero deg for next layer
    for (int i = gt; i < k; i += gs) g_deg[i] = 0;
    gridbar();
    if (bid == 0 && tid < H) {
        float s = __ldcg(&g_sum[tid]);
        float m = __ldcg(&g_max[tid]);
        g_rtot[tid] += s / (float)k;
        g_rtot[H + tid] += m;
        g_sum[tid] = 0.0f;
        g_max[tid] = NEGV;
    }
}

// ---------------- final MLP + log_softmax ----------------
__global__ void k_mlp(const float* __restrict__ M1, const float* __restrict__ bm1,
                      const float* __restrict__ M2, const float* __restrict__ bm2,
                      const float* __restrict__ M3, const float* __restrict__ bm3,
                      float* __restrict__ out) {
    __shared__ float r[256];
    __shared__ float y1[128];
    __shared__ float y2[64];
    __shared__ float y3[10];
    int t = threadIdx.x;
    r[t] = g_rtot[t];
    __syncthreads();
    if (t < 128) {
        float a = bm1[t];
        for (int i = 0; i < 256; i++) a += r[i] * M1[i * 128 + t];
        y1[t] = fmaxf(a, 0.0f);
    }
    __syncthreads();
    if (t < 64) {
        float a = bm2[t];
        for (int i = 0; i < 128; i++) a += y1[i] * M2[i * 64 + t];
        y2[t] = fmaxf(a, 0.0f);
    }
    __syncthreads();
    if (t < 10) {
        float a = bm3[t];
        for (int i = 0; i < 64; i++) a += y2[i] * M3[i * 10 + t];
        y3[t] = a;
    }
    __syncthreads();
    if (t == 0) {
        float m = y3[0];
        for (int j = 1; j < 10; j++) m = fmaxf(m, y3[j]);
        float s = 0.0f;
        for (int j = 0; j < 10; j++) s += expf(y3[j] - m);
        float l = logf(s);
        for (int j = 0; j < 10; j++) out[j] = y3[j] - m - l;
    }
}

// ---------------- launch ----------------
extern "C" void kernel_launch(void* const* d_in, const int* in_sizes, int n_in,
                              void* d_out, int out_size) {
    const float* x = (const float*)d_in[0];
    const void* ei = d_in[1];
    const float* W[3]  = {(const float*)d_in[2], (const float*)d_in[6], (const float*)d_in[10]};
    const float* b[3]  = {(const float*)d_in[3], (const float*)d_in[7], (const float*)d_in[11]};
    const float* ws[3] = {(const float*)d_in[4], (const float*)d_in[8], (const float*)d_in[12]};
    const float* bs[3] = {(const float*)d_in[5], (const float*)d_in[9], (const float*)d_in[13]};
    const float* M1 = (const float*)d_in[14]; const float* bm1 = (const float*)d_in[15];
    const float* M2 = (const float*)d_in[16]; const float* bm2 = (const float*)d_in[17];
    const float* M3 = (const float*)d_in[18]; const float* bm3 = (const float*)d_in[19];
    float* out = (float*)d_out;

    int *ea_s, *ea_d, *eb_s, *eb_d;
    cudaGetSymbolAddress((void**)&ea_s, g_ea_src);
    cudaGetSymbolAddress((void**)&ea_d, g_ea_dst);
    cudaGetSymbolAddress((void**)&eb_s, g_eb_src);
    cudaGetSymbolAddress((void**)&eb_d, g_eb_dst);
    float* gx;
    cudaGetSymbolAddress((void**)&gx, g_x);

    const int nl[3] = {100000, 50000, 25000};
    const int kk[3] = {50000, 25000, 12500};
    const int gE = (EE + 255) / 256;

    k_detect<<<1, 32>>>(ei);
    k_convert<<<gE, 256>>>(ei);
    k_init<<<(NN + 255) / 256, 256>>>();

    for (int l = 0; l < 3; l++) {
        const int n = nl[l];
        int* ps = (l & 1) ? eb_s : ea_s;
        int* pd = (l & 1) ? eb_d : ea_d;
        int* qs = (l & 1) ? ea_s : eb_s;
        int* qd = (l & 1) ? ea_d : eb_d;
        const int ucm = (l > 0) ? 1 : 0;
        const float* A = (l == 0) ? x : gx;

        k_deg<<<gE, 256>>>(ps, pd, l, ucm);
        k_scan_dinv<<<SB, ST>>>(n, l + 1);
        k_scatter<<<gE, 256>>>(ps, pd, qs, qd, l, ucm);
        k_gemm<<<(n + 127) / 128, 256>>>(A, W[l], n);
        k_agg<<<(n + 7) / 8, 256>>>(b[l], ws[l], qs, n);
        k_score<<<(n + 255) / 256, 256>>>(qs, bs[l], n);
        k_select<<<SB, ST>>>(n, kk[l]);
    }
    k_mlp<<<1, 256>>>(M1, bm1, M2, bm2, M3, bm3, out);
}